// round 7
// baseline (speedup 1.0000x reference)
#include <cuda_runtime.h>
#include <cuda_fp16.h>
#include <cstdint>

// VQ-VAE quantization via warp-mma (fp16 approx + exact fp32 margin-rescore)
//   x   [32, 64, 64, 64] fp32  (B, C, H, W)
//   emb [1024, 64] fp32        (K, C)
// out fp32: o[8388608] | loss[1] | indices[131072]

#define NPOS      131072
#define CDIM      64
#define KCODES    1024
#define HW        4096
#define XSIZE     8388608
#define TILE_M    128
#define THREADS   256
#define NBLOCKS   (NPOS / TILE_M)     // 1024
#define NCHUNKS   8                   // 128 codes per chunk
#define MARGIN    2.0f                // 8x worst-case fp16 distance error bound

__device__ __align__(16) unsigned short g_ehf[KCODES * CDIM];  // fp16 codebook
__device__ float g_e2[KCODES];
__device__ float g_partials[NBLOCKS];

// ---- smem layout (bytes) ----
#define SM_B      0            // fp16 codebook, 1024 rows x 128B (swizzled)   131072
#define SM_A16    131072       // fp16 A tile, 128 rows x 128B (swizzled)       16384
#define SM_A32    147456       // fp32 A tile, 128 rows x 256B                  32768
#define SM_E2     180224       // fp32 e2[1024]                                  4096
#define SM_IDX    184320       // int idx[128]                                    512
#define SM_RED    184832       // float red[256]                                 1024
#define SM_TOTAL  185856

// ---------------- helpers ----------------
__device__ __forceinline__ uint32_t smem_u32(const void* p) {
    uint32_t a;
    asm("{ .reg .u64 t; cvta.to.shared.u64 t, %1; cvt.u32.u64 %0, t; }" : "=r"(a) : "l"(p));
    return a;
}
__device__ __forceinline__ void ldmx4(uint32_t* r, uint32_t addr) {
    asm volatile("ldmatrix.sync.aligned.m8n8.x4.shared.b16 {%0,%1,%2,%3}, [%4];"
        : "=r"(r[0]), "=r"(r[1]), "=r"(r[2]), "=r"(r[3]) : "r"(addr));
}
__device__ __forceinline__ void mma16816(float* c, const uint32_t* a, uint32_t b0, uint32_t b1) {
    asm("mma.sync.aligned.m16n8k16.row.col.f32.f16.f16.f32 "
        "{%0,%1,%2,%3}, {%4,%5,%6,%7}, {%8,%9}, {%0,%1,%2,%3};"
        : "+f"(c[0]), "+f"(c[1]), "+f"(c[2]), "+f"(c[3])
        : "r"(a[0]), "r"(a[1]), "r"(a[2]), "r"(a[3]), "r"(b0), "r"(b1));
}

// exact fp32 rescore of code k against row z (smem fp32), update (best, bidx)
// NOTE: association matches R1's known-good inner loop exactly.
__device__ __forceinline__ void rescore(int k, const float* __restrict__ zrow,
                                        const float* __restrict__ emb,
                                        const float* __restrict__ s_e2,
                                        float& best, int& bidx) {
    const float4* e4 = reinterpret_cast<const float4*>(emb + k * CDIM);
    const float4* z4 = reinterpret_cast<const float4*>(zrow);
    float a0 = 0.f, a1 = 0.f, a2 = 0.f, a3 = 0.f;
#pragma unroll
    for (int i = 0; i < 16; i++) {
        float4 e = __ldg(&e4[i]);
        float4 z = z4[i];
        a0 = fmaf(z.x, e.x, a0);
        a1 = fmaf(z.y, e.y, a1);
        a2 = fmaf(z.z, e.z, a2);
        a3 = fmaf(z.w, e.w, a3);
    }
    float dot = (a0 + a1) + (a2 + a3);
    float d = s_e2[k] - 2.0f * dot;
    if (d < best || (d == best && k < bidx)) { best = d; bidx = k; }
}

// ---------------------------------------------------------------------------
// Pass 0a: ||e||^2 — VERBATIM numerics from the known-passing R1 e2_kernel
// ---------------------------------------------------------------------------
__global__ void e2_kernel(const float* __restrict__ emb) {
    int k = blockIdx.x * blockDim.x + threadIdx.x;
    if (k < KCODES) {
        const float4* row = reinterpret_cast<const float4*>(emb + k * CDIM);
        float s = 0.f;
#pragma unroll
        for (int i = 0; i < 16; i++) {
            float4 v = row[i];
            s += v.x * v.x + v.y * v.y + v.z * v.z + v.w * v.w;
        }
        g_e2[k] = s;
    }
}

// ---------------------------------------------------------------------------
// Pass 0b: fp16 codebook
// ---------------------------------------------------------------------------
__global__ void cvt_kernel(const float* __restrict__ emb) {
    int i = blockIdx.x * blockDim.x + threadIdx.x;
    if (i < KCODES * CDIM / 2) {
        float2 f = reinterpret_cast<const float2*>(emb)[i];
        __half2 h = __floats2half2_rn(f.x, f.y);
        reinterpret_cast<uint32_t*>(g_ehf)[i] = *reinterpret_cast<uint32_t*>(&h);
    }
}

// ---------------------------------------------------------------------------
// Pass 1: mma distance GEMM + margin-rescored argmin + fused output/loss
// ---------------------------------------------------------------------------
__global__ __launch_bounds__(THREADS, 1)
void vq_kernel(const float* __restrict__ x,
               const float* __restrict__ emb,
               float* __restrict__ out) {
    extern __shared__ char smem[];
    const uint32_t sbase = smem_u32(smem);
    float* s_e2  = reinterpret_cast<float*>(smem + SM_E2);
    float* s_A32 = reinterpret_cast<float*>(smem + SM_A32);
    int*   s_idx = reinterpret_cast<int*>(smem + SM_IDX);
    float* s_red = reinterpret_cast<float*>(smem + SM_RED);

    const int tid  = threadIdx.x;
    const int lane = tid & 31;
    const int wid  = tid >> 5;

    // ---- fill B (fp16 codebook, swizzled rows of 128B) ----
    {
        const uint4* src = reinterpret_cast<const uint4*>(g_ehf);
#pragma unroll
        for (int i = tid; i < KCODES * 8; i += THREADS) {   // 16B pieces
            int row = i >> 3, sect = i & 7;
            uint4 v = __ldg(&src[i]);
            *reinterpret_cast<uint4*>(smem + SM_B + row * 128 + ((sect ^ (row & 7)) << 4)) = v;
        }
    }
    // ---- e2 ----
#pragma unroll
    for (int i = tid; i < KCODES; i += THREADS) s_e2[i] = g_e2[i];

    // ---- fill A (fp32 + fp16 swizzled); row r = position, cols = channels ----
    {
        const int r    = tid & 127;
        const int half = tid >> 7;                 // 0: ch 0..31, 1: ch 32..63
        const int p    = blockIdx.x * TILE_M + r;
        const int b    = p >> 12;
        const int hw   = p & (HW - 1);
        const float* xp = x + (size_t)b * CDIM * HW + hw;
#pragma unroll
        for (int s = 0; s < 4; s++) {
            int sect = half * 4 + s;               // 8 channels per sect
            float f[8];
#pragma unroll
            for (int j = 0; j < 8; j++) f[j] = __ldg(xp + (sect * 8 + j) * HW);
            uint4 v;
            uint32_t* vp = &v.x;
#pragma unroll
            for (int j = 0; j < 4; j++) {
                __half2 h = __floats2half2_rn(f[2 * j], f[2 * j + 1]);
                vp[j] = *reinterpret_cast<uint32_t*>(&h);
            }
            *reinterpret_cast<uint4*>(smem + SM_A16 + r * 128 + ((sect ^ (r & 7)) << 4)) = v;
#pragma unroll
            for (int j = 0; j < 8; j++) s_A32[r * CDIM + sect * 8 + j] = f[j];
        }
    }
    __syncthreads();

    // ---- per-warp GEMM: rows m0..m0+15 vs all 1024 codes ----
    const int m0   = wid * 16;
    const int qrow = lane >> 2;
    const int qcol = (lane & 3) * 2;
    const int rA   = m0 + qrow;        // this thread's two rows
    const int rB   = rA + 8;
    const float* zA = s_A32 + rA * CDIM;
    const float* zB = s_A32 + rB * CDIM;

    // A fragments (once): ldmatrix.x4 per k-step
    uint32_t afr[4][4];
    {
        const uint32_t arow = (uint32_t)(m0 + (lane & 7) + ((lane >> 3) & 1) * 8);
        const uint32_t asb  = (uint32_t)(lane >> 4);
        const uint32_t asx  = (uint32_t)(lane & 7);
#pragma unroll
        for (int ks = 0; ks < 4; ks++)
            ldmx4(afr[ks], sbase + SM_A16 + arow * 128 + ((((ks << 1) | asb) ^ asx) << 4));
    }

    // B lane addressing constants
    const uint32_t brow_off = (uint32_t)(((lane >> 4) * 8 + (lane & 7)) * 128);
    const uint32_t bsb      = (uint32_t)((lane >> 3) & 1);
    const uint32_t bsx      = (uint32_t)(lane & 7);

    float bestA = 3.4e38f, bestB = 3.4e38f;
    int   idxA  = 0,       idxB  = 0;

#pragma unroll 1
    for (int cb = 0; cb < NCHUNKS; cb++) {
        const int n0 = cb * 128;
        float c[16][4];
#pragma unroll
        for (int t = 0; t < 16; t++)
#pragma unroll
            for (int j = 0; j < 4; j++) c[t][j] = 0.f;

#pragma unroll
        for (int tp = 0; tp < 8; tp++) {            // 16 codes per pair
            const uint32_t nb = (uint32_t)(n0 + tp * 16);
            uint32_t bfr[4][4];
#pragma unroll
            for (int ks = 0; ks < 4; ks++)
                ldmx4(bfr[ks], sbase + SM_B + nb * 128 + brow_off
                               + ((((ks << 1) | bsb) ^ bsx) << 4));
#pragma unroll
            for (int ks = 0; ks < 4; ks++) {
                mma16816(c[tp * 2],     afr[ks], bfr[ks][0], bfr[ks][1]);
                mma16816(c[tp * 2 + 1], afr[ks], bfr[ks][2], bfr[ks][3]);
            }
        }

        // epilogue: d = e2 - 2*dot (approx)
#pragma unroll
        for (int t = 0; t < 16; t++) {
            float2 e2v = *reinterpret_cast<const float2*>(&s_e2[n0 + t * 8 + qcol]);
            c[t][0] = fmaf(c[t][0], -2.f, e2v.x);
            c[t][1] = fmaf(c[t][1], -2.f, e2v.y);
            c[t][2] = fmaf(c[t][2], -2.f, e2v.x);
            c[t][3] = fmaf(c[t][3], -2.f, e2v.y);
        }

        // chunk 0: seed best with exact d of the approx-argmin (avoid +inf flood)
        if (cb == 0) {
            float sA = c[0][0]; int siA = qcol;
            float sB = c[0][2]; int siB = qcol;
#pragma unroll
            for (int t = 0; t < 16; t++) {
                int k0 = t * 8 + qcol;
                if (c[t][0] < sA) { sA = c[t][0]; siA = k0; }
                if (c[t][1] < sA) { sA = c[t][1]; siA = k0 + 1; }
                if (c[t][2] < sB) { sB = c[t][2]; siB = k0; }
                if (c[t][3] < sB) { sB = c[t][3]; siB = k0 + 1; }
            }
            rescore(siA, zA, emb, s_e2, bestA, idxA);
            rescore(siB, zB, emb, s_e2, bestB, idxB);
        }

        // chunk-min skip + per-element margin rescore
        float mA = 3.4e38f, mB = 3.4e38f;
#pragma unroll
        for (int t = 0; t < 16; t++) {
            mA = fminf(mA, fminf(c[t][0], c[t][1]));
            mB = fminf(mB, fminf(c[t][2], c[t][3]));
        }
        if (mA < bestA + MARGIN) {
#pragma unroll
            for (int t = 0; t < 16; t++) {
                if (c[t][0] < bestA + MARGIN) rescore(n0 + t * 8 + qcol,     zA, emb, s_e2, bestA, idxA);
                if (c[t][1] < bestA + MARGIN) rescore(n0 + t * 8 + qcol + 1, zA, emb, s_e2, bestA, idxA);
            }
        }
        if (mB < bestB + MARGIN) {
#pragma unroll
            for (int t = 0; t < 16; t++) {
                if (c[t][2] < bestB + MARGIN) rescore(n0 + t * 8 + qcol,     zB, emb, s_e2, bestB, idxB);
                if (c[t][3] < bestB + MARGIN) rescore(n0 + t * 8 + qcol + 1, zB, emb, s_e2, bestB, idxB);
            }
        }
    }

    // reduce across the 4 lanes of each row quad (exact fp32 values + idx tiebreak)
#pragma unroll
    for (int off = 1; off < 4; off <<= 1) {
        float ob = __shfl_xor_sync(0xffffffffu, bestA, off);
        int   oi = __shfl_xor_sync(0xffffffffu, idxA,  off);
        if (ob < bestA || (ob == bestA && oi < idxA)) { bestA = ob; idxA = oi; }
        ob = __shfl_xor_sync(0xffffffffu, bestB, off);
        oi = __shfl_xor_sync(0xffffffffu, idxB,  off);
        if (ob < bestB || (ob == bestB && oi < idxB)) { bestB = ob; idxB = oi; }
    }
    if ((lane & 3) == 0) { s_idx[rA] = idxA; s_idx[rB] = idxB; }
    __syncthreads();

    // ---- output: o = x + (e - x), indices, loss partial ----
    {
        const int r    = tid & 127;
        const int half = tid >> 7;
        const int p    = blockIdx.x * TILE_M + r;
        const int b    = p >> 12;
        const int hw   = p & (HW - 1);
        const int k    = s_idx[r];
        const float* er = emb + k * CDIM;
        const float* zr = s_A32 + r * CDIM;
        float* op = out + (size_t)b * CDIM * HW + hw;
        float ls = 0.f;
#pragma unroll
        for (int j = 0; j < 32; j++) {
            int ch = half * 32 + j;
            float xv = zr[ch];
            float ev = __ldg(er + ch);
            op[ch * HW] = xv + (ev - xv);           // match reference fp32 ops
            float d = xv - ev;
            ls = fmaf(d, d, ls);
        }
        if (half == 0) out[XSIZE + 1 + p] = (float)k;

        s_red[tid] = ls;
        __syncthreads();
#pragma unroll
        for (int s = THREADS / 2; s > 0; s >>= 1) {
            if (tid < s) s_red[tid] += s_red[tid + s];
            __syncthreads();
        }
        if (tid == 0) g_partials[blockIdx.x] = s_red[0];
    }
}

// ---------------------------------------------------------------------------
// Pass 2: deterministic loss finalize
// ---------------------------------------------------------------------------
__global__ void finalize_kernel(float* __restrict__ out) {
    __shared__ double sd[NBLOCKS];
    int t = threadIdx.x;
    sd[t] = (double)g_partials[t];
    __syncthreads();
#pragma unroll
    for (int s = NBLOCKS / 2; s > 0; s >>= 1) {
        if (t < s) sd[t] += sd[t + s];
        __syncthreads();
    }
    if (t == 0) out[XSIZE] = (float)(1.25 * sd[0] / (double)XSIZE);
}

// ---------------------------------------------------------------------------
extern "C" void kernel_launch(void* const* d_in, const int* in_sizes, int n_in,
                              void* d_out, int out_size) {
    const float* x   = (const float*)d_in[0];
    const float* emb = (const float*)d_in[1];
    if (n_in >= 2 && in_sizes[0] == KCODES * CDIM && in_sizes[1] == XSIZE) {
        const float* t = x; x = emb; emb = t;
    }
    float* out = (float*)d_out;

    cudaFuncSetAttribute(vq_kernel, cudaFuncAttributeMaxDynamicSharedMemorySize, SM_TOTAL);

    e2_kernel<<<(KCODES + 255) / 256, 256>>>(emb);
    cvt_kernel<<<(KCODES * CDIM / 2 + 255) / 256, 256>>>(emb);
    vq_kernel<<<NBLOCKS, THREADS, SM_TOTAL>>>(x, emb, out);
    finalize_kernel<<<1, NBLOCKS>>>(out);
}

// round 13
// speedup vs baseline: 2.1771x; 2.1771x over previous
#include <cuda_runtime.h>
#include <cuda_fp16.h>
#include <cstdint>

// VQ-VAE quantization via warp-mma (fp16 approx + exact fp32 margin-rescore)
//   x   [32, 64, 64, 64] fp32  (B, C, H, W)
//   emb [1024, 64] fp32        (K, C)
// out fp32: o[8388608] | loss[1] | indices[131072]

#define NPOS      131072
#define CDIM      64
#define KCODES    1024
#define HW        4096
#define XSIZE     8388608
#define TILE_M    128
#define THREADS   256
#define NBLOCKS   (NPOS / TILE_M)     // 1024
#define NCHUNKS   8                   // 128 codes per chunk
#define MARGIN    2.0f                // >> worst-case fp16 distance error bound

__device__ __align__(16) unsigned short g_ehf[KCODES * CDIM];  // fp16 codebook
__device__ float g_e2[KCODES];
__device__ float g_partials[NBLOCKS];

// ---- smem layout (bytes) ----
#define SM_A16    0            // fp16 A tile, 128 rows x 128B (swizzled)     16384
#define SM_A32    16384        // fp32 A tile, 128 rows x 256B                32768
#define SM_B      49152        // fp16 B chunk, double buffer 2 x 16384       32768
#define SM_E2     81920        // fp32 e2[1024]                                4096
#define SM_IDX    86016        // int idx[128]                                  512
#define SM_RED    86528        // float red[256]                               1024
#define SM_TOTAL  87552

// ---------------- helpers ----------------
__device__ __forceinline__ uint32_t smem_u32(const void* p) {
    uint32_t a;
    asm("{ .reg .u64 t; cvta.to.shared.u64 t, %1; cvt.u32.u64 %0, t; }" : "=r"(a) : "l"(p));
    return a;
}
__device__ __forceinline__ void ldmx4(uint32_t* r, uint32_t addr) {
    asm volatile("ldmatrix.sync.aligned.m8n8.x4.shared.b16 {%0,%1,%2,%3}, [%4];"
        : "=r"(r[0]), "=r"(r[1]), "=r"(r[2]), "=r"(r[3]) : "r"(addr));
}
__device__ __forceinline__ void mma16816(float* c, const uint32_t* a, uint32_t b0, uint32_t b1) {
    asm("mma.sync.aligned.m16n8k16.row.col.f32.f16.f16.f32 "
        "{%0,%1,%2,%3}, {%4,%5,%6,%7}, {%8,%9}, {%0,%1,%2,%3};"
        : "+f"(c[0]), "+f"(c[1]), "+f"(c[2]), "+f"(c[3])
        : "r"(a[0]), "r"(a[1]), "r"(a[2]), "r"(a[3]), "r"(b0), "r"(b1));
}

// exact fp32 rescore of code k against row z (smem fp32) — association matches
// the known-good R1/R7 exact path verbatim.
__device__ __forceinline__ void rescore(int k, const float* __restrict__ zrow,
                                        const float* __restrict__ emb,
                                        const float* __restrict__ s_e2,
                                        float& best, int& bidx) {
    const float4* e4 = reinterpret_cast<const float4*>(emb + k * CDIM);
    const float4* z4 = reinterpret_cast<const float4*>(zrow);
    float a0 = 0.f, a1 = 0.f, a2 = 0.f, a3 = 0.f;
#pragma unroll
    for (int i = 0; i < 16; i++) {
        float4 e = __ldg(&e4[i]);
        float4 z = z4[i];
        a0 = fmaf(z.x, e.x, a0);
        a1 = fmaf(z.y, e.y, a1);
        a2 = fmaf(z.z, e.z, a2);
        a3 = fmaf(z.w, e.w, a3);
    }
    float dot = (a0 + a1) + (a2 + a3);
    float d = s_e2[k] - 2.0f * dot;
    if (d < best || (d == best && k < bidx)) { best = d; bidx = k; }
}

// cp.async prefetch of one 128-code fp16 chunk into a swizzled smem buffer
__device__ __forceinline__ void prefetch_chunk(uint32_t dstbase, int k0, int tid) {
#pragma unroll
    for (int i = tid; i < 1024; i += THREADS) {   // 1024 x 16B pieces
        int row = i >> 3, sect = i & 7;
        uint32_t dst = dstbase + row * 128 + ((sect ^ (row & 7)) << 4);
        const char* src = (const char*)g_ehf + (size_t)(k0 + row) * 128 + sect * 16;
        asm volatile("cp.async.cg.shared.global [%0], [%1], 16;" :: "r"(dst), "l"(src));
    }
}

// ---------------------------------------------------------------------------
// Pass 0a: ||e||^2 — VERBATIM numerics from the known-passing R1 e2_kernel
// ---------------------------------------------------------------------------
__global__ void e2_kernel(const float* __restrict__ emb) {
    int k = blockIdx.x * blockDim.x + threadIdx.x;
    if (k < KCODES) {
        const float4* row = reinterpret_cast<const float4*>(emb + k * CDIM);
        float s = 0.f;
#pragma unroll
        for (int i = 0; i < 16; i++) {
            float4 v = row[i];
            s += v.x * v.x + v.y * v.y + v.z * v.z + v.w * v.w;
        }
        g_e2[k] = s;
    }
}

// ---------------------------------------------------------------------------
// Pass 0b: fp16 codebook
// ---------------------------------------------------------------------------
__global__ void cvt_kernel(const float* __restrict__ emb) {
    int i = blockIdx.x * blockDim.x + threadIdx.x;
    if (i < KCODES * CDIM / 2) {
        float2 f = reinterpret_cast<const float2*>(emb)[i];
        __half2 h = __floats2half2_rn(f.x, f.y);
        reinterpret_cast<uint32_t*>(g_ehf)[i] = *reinterpret_cast<uint32_t*>(&h);
    }
}

// ---------------------------------------------------------------------------
// Pass 1: mma distance GEMM + mask-based margin rescore + fused output/loss
// ---------------------------------------------------------------------------
__global__ __launch_bounds__(THREADS, 2)
void vq_kernel(const float* __restrict__ x,
               const float* __restrict__ emb,
               float* __restrict__ out) {
    extern __shared__ char smem[];
    const uint32_t sbase = smem_u32(smem);
    float* s_e2  = reinterpret_cast<float*>(smem + SM_E2);
    float* s_A32 = reinterpret_cast<float*>(smem + SM_A32);
    int*   s_idx = reinterpret_cast<int*>(smem + SM_IDX);
    float* s_red = reinterpret_cast<float*>(smem + SM_RED);

    const int tid  = threadIdx.x;
    const int lane = tid & 31;
    const int wid  = tid >> 5;

    // kick off B chunk 0 load early (overlaps all the fills below)
    prefetch_chunk(sbase + SM_B, 0, tid);
    asm volatile("cp.async.commit_group;" ::: "memory");

    // ---- e2 ----
#pragma unroll
    for (int i = tid; i < KCODES; i += THREADS) s_e2[i] = g_e2[i];

    // ---- fill A (fp32 + fp16 swizzled); row r = position, cols = channels ----
    {
        const int r    = tid & 127;
        const int half = tid >> 7;                 // 0: ch 0..31, 1: ch 32..63
        const int p    = blockIdx.x * TILE_M + r;
        const int b    = p >> 12;
        const int hw   = p & (HW - 1);
        const float* xp = x + (size_t)b * CDIM * HW + hw;
#pragma unroll
        for (int s = 0; s < 4; s++) {
            int sect = half * 4 + s;               // 8 channels per sect
            float f[8];
#pragma unroll
            for (int j = 0; j < 8; j++) f[j] = __ldg(xp + (sect * 8 + j) * HW);
            uint4 v;
            uint32_t* vp = &v.x;
#pragma unroll
            for (int j = 0; j < 4; j++) {
                __half2 h = __floats2half2_rn(f[2 * j], f[2 * j + 1]);
                vp[j] = *reinterpret_cast<uint32_t*>(&h);
            }
            *reinterpret_cast<uint4*>(smem + SM_A16 + r * 128 + ((sect ^ (r & 7)) << 4)) = v;
#pragma unroll
            for (int j = 0; j < 8; j++) s_A32[r * CDIM + sect * 8 + j] = f[j];
        }
    }
    __syncthreads();   // A16/A32/e2 visible

    // ---- per-warp GEMM setup: rows m0..m0+15 ----
    const int m0   = wid * 16;
    const int qrow = lane >> 2;
    const int qcol = (lane & 3) * 2;
    const int rA   = m0 + qrow;
    const int rB   = rA + 8;
    const float* zA = s_A32 + rA * CDIM;
    const float* zB = s_A32 + rB * CDIM;

    // A fragments (once)
    uint32_t afr[4][4];
    {
        const uint32_t arow = (uint32_t)(m0 + (lane & 7) + ((lane >> 3) & 1) * 8);
        const uint32_t asb  = (uint32_t)(lane >> 4);
        const uint32_t asx  = (uint32_t)(lane & 7);
#pragma unroll
        for (int ks = 0; ks < 4; ks++)
            ldmx4(afr[ks], sbase + SM_A16 + arow * 128 + ((((ks << 1) | asb) ^ asx) << 4));
    }

    // B lane addressing constants (rows local to chunk buffer)
    const uint32_t brow_off = (uint32_t)(((lane >> 4) * 8 + (lane & 7)) * 128);
    const uint32_t bsb      = (uint32_t)((lane >> 3) & 1);
    const uint32_t bsx      = (uint32_t)(lane & 7);

    float bestA = 3.4e38f, bestB = 3.4e38f;
    int   idxA  = 0,       idxB  = 0;

#pragma unroll 1
    for (int cb = 0; cb < NCHUNKS; cb++) {
        if (cb + 1 < NCHUNKS) {
            prefetch_chunk(sbase + SM_B + ((cb + 1) & 1) * 16384, (cb + 1) * 128, tid);
            asm volatile("cp.async.commit_group;" ::: "memory");
            asm volatile("cp.async.wait_group 1;" ::: "memory");
        } else {
            asm volatile("cp.async.wait_group 0;" ::: "memory");
        }
        __syncthreads();   // buf[cb&1] ready for all warps

        const uint32_t bufbase = sbase + SM_B + (cb & 1) * 16384;
        const int n0 = cb * 128;

#pragma unroll 1
        for (int sg = 0; sg < 2; sg++) {          // 64 codes per segment
            float c[8][4];
#pragma unroll
            for (int t = 0; t < 8; t++)
#pragma unroll
                for (int j = 0; j < 4; j++) c[t][j] = 0.f;

#pragma unroll
            for (int tp = 0; tp < 4; tp++) {      // 16 codes per pair
                const uint32_t nbl = (uint32_t)(sg * 64 + tp * 16);
                uint32_t bfr[4][4];
#pragma unroll
                for (int ks = 0; ks < 4; ks++)
                    ldmx4(bfr[ks], bufbase + nbl * 128 + brow_off
                                   + ((((ks << 1) | bsb) ^ bsx) << 4));
#pragma unroll
                for (int ks = 0; ks < 4; ks++) {
                    mma16816(c[tp * 2],     afr[ks], bfr[ks][0], bfr[ks][1]);
                    mma16816(c[tp * 2 + 1], afr[ks], bfr[ks][2], bfr[ks][3]);
                }
            }

            const int kb = n0 + sg * 64;
            // d = e2 - 2*dot (approx)
#pragma unroll
            for (int t = 0; t < 8; t++) {
                float2 e2v = *reinterpret_cast<const float2*>(&s_e2[kb + t * 8 + qcol]);
                c[t][0] = fmaf(c[t][0], -2.f, e2v.x);
                c[t][1] = fmaf(c[t][1], -2.f, e2v.y);
                c[t][2] = fmaf(c[t][2], -2.f, e2v.x);
                c[t][3] = fmaf(c[t][3], -2.f, e2v.y);
            }

            // first segment: seed best with exact d of the approx-argmin
            if (cb == 0 && sg == 0) {
                float sA = c[0][0]; int siA = kb + qcol;
                float sB = c[0][2]; int siB = kb + qcol;
#pragma unroll
                for (int t = 0; t < 8; t++) {
                    int k0i = kb + t * 8 + qcol;
                    if (c[t][0] < sA) { sA = c[t][0]; siA = k0i; }
                    if (c[t][1] < sA) { sA = c[t][1]; siA = k0i + 1; }
                    if (c[t][2] < sB) { sB = c[t][2]; siB = k0i; }
                    if (c[t][3] < sB) { sB = c[t][3]; siB = k0i + 1; }
                }
                rescore(siA, zA, emb, s_e2, bestA, idxA);
                rescore(siB, zB, emb, s_e2, bestB, idxB);
            }

            // qualification masks (c[] dies here — no live accums across rescore)
            const float thrA = bestA + MARGIN, thrB = bestB + MARGIN;
            unsigned mA = 0, mB = 0;
#pragma unroll
            for (int t = 0; t < 8; t++) {
                mA |= (c[t][0] < thrA ? 1u : 0u) << (2 * t);
                mA |= (c[t][1] < thrA ? 2u : 0u) << (2 * t);
                mB |= (c[t][2] < thrB ? 1u : 0u) << (2 * t);
                mB |= (c[t][3] < thrB ? 2u : 0u) << (2 * t);
            }
            while (mA) {
                int bpos = __ffs(mA) - 1; mA &= mA - 1;
                rescore(kb + (bpos >> 1) * 8 + qcol + (bpos & 1), zA, emb, s_e2, bestA, idxA);
            }
            while (mB) {
                int bpos = __ffs(mB) - 1; mB &= mB - 1;
                rescore(kb + (bpos >> 1) * 8 + qcol + (bpos & 1), zB, emb, s_e2, bestB, idxB);
            }
        }
        __syncthreads();   // all warps done with buf[cb&1] before it is refilled
    }

    // reduce across the 4 lanes of each row quad (exact fp32 values + idx tiebreak)
#pragma unroll
    for (int off = 1; off < 4; off <<= 1) {
        float ob = __shfl_xor_sync(0xffffffffu, bestA, off);
        int   oi = __shfl_xor_sync(0xffffffffu, idxA,  off);
        if (ob < bestA || (ob == bestA && oi < idxA)) { bestA = ob; idxA = oi; }
        ob = __shfl_xor_sync(0xffffffffu, bestB, off);
        oi = __shfl_xor_sync(0xffffffffu, idxB,  off);
        if (ob < bestB || (ob == bestB && oi < idxB)) { bestB = ob; idxB = oi; }
    }
    if ((lane & 3) == 0) { s_idx[rA] = idxA; s_idx[rB] = idxB; }
    __syncthreads();

    // ---- output: o = x + (e - x), indices, loss partial ----
    {
        const int r    = tid & 127;
        const int half = tid >> 7;
        const int p    = blockIdx.x * TILE_M + r;
        const int b    = p >> 12;
        const int hw   = p & (HW - 1);
        const int k    = s_idx[r];
        const float* er = emb + k * CDIM;
        const float* zr = s_A32 + r * CDIM;
        float* op = out + (size_t)b * CDIM * HW + hw;
        float ls = 0.f;
#pragma unroll
        for (int j = 0; j < 32; j++) {
            int ch = half * 32 + j;
            float xv = zr[ch];
            float ev = __ldg(er + ch);
            op[ch * HW] = xv + (ev - xv);           // match reference fp32 ops
            float d = xv - ev;
            ls = fmaf(d, d, ls);
        }
        if (half == 0) out[XSIZE + 1 + p] = (float)k;

        s_red[tid] = ls;
        __syncthreads();
#pragma unroll
        for (int s = THREADS / 2; s > 0; s >>= 1) {
            if (tid < s) s_red[tid] += s_red[tid + s];
            __syncthreads();
        }
        if (tid == 0) g_partials[blockIdx.x] = s_red[0];
    }
}

// ---------------------------------------------------------------------------
// Pass 2: deterministic loss finalize
// ---------------------------------------------------------------------------
__global__ void finalize_kernel(float* __restrict__ out) {
    __shared__ double sd[NBLOCKS];
    int t = threadIdx.x;
    sd[t] = (double)g_partials[t];
    __syncthreads();
#pragma unroll
    for (int s = NBLOCKS / 2; s > 0; s >>= 1) {
        if (t < s) sd[t] += sd[t + s];
        __syncthreads();
    }
    if (t == 0) out[XSIZE] = (float)(1.25 * sd[0] / (double)XSIZE);
}

// ---------------------------------------------------------------------------
extern "C" void kernel_launch(void* const* d_in, const int* in_sizes, int n_in,
                              void* d_out, int out_size) {
    const float* x   = (const float*)d_in[0];
    const float* emb = (const float*)d_in[1];
    if (n_in >= 2 && in_sizes[0] == KCODES * CDIM && in_sizes[1] == XSIZE) {
        const float* t = x; x = emb; emb = t;
    }
    float* out = (float*)d_out;

    cudaFuncSetAttribute(vq_kernel, cudaFuncAttributeMaxDynamicSharedMemorySize, SM_TOTAL);

    e2_kernel<<<(KCODES + 255) / 256, 256>>>(emb);
    cvt_kernel<<<(KCODES * CDIM / 2 + 255) / 256, 256>>>(emb);
    vq_kernel<<<NBLOCKS, THREADS, SM_TOTAL>>>(x, emb, out);
    finalize_kernel<<<1, NBLOCKS>>>(out);
}

// round 15
// speedup vs baseline: 3.1587x; 1.4509x over previous
#include <cuda_runtime.h>
#include <cuda_fp16.h>
#include <cstdint>

// VQ-VAE quantization via warp-mma (fp16 approx + deferred exact fp32 rescore)
//   x   [32, 64, 64, 64] fp32  (B, C, H, W)
//   emb [1024, 64] fp32        (K, C)
// out fp32: o[8388608] | loss[1] | indices[131072]

#define NPOS      131072
#define CDIM      64
#define KCODES    1024
#define HW        4096
#define XSIZE     8388608
#define TILE_M    128
#define THREADS   256
#define NBLOCKS   (NPOS / TILE_M)     // 1024
#define NCHUNKS   8                   // 128 codes per chunk
#define MARGIN    2.0f                // >> 2x worst-case fp16 distance error
#define CAP       8                   // candidate buffer capacity per row

__device__ __align__(16) unsigned short g_ehf[KCODES * CDIM];  // fp16 codebook
__device__ float g_e2[KCODES];
__device__ float g_partials[NBLOCKS];

// ---- smem layout (bytes) ----
#define SM_A16    0            // fp16 A tile, 128 rows x 128B (swizzled)     16384
#define SM_A32    16384        // fp32 A tile, 128 rows x 256B                32768
#define SM_B      49152        // fp16 B chunk, 3-buffer ring 3 x 16384       49152
#define SM_E2     98304        // fp32 e2[1024]                                4096
#define SM_IDX    102400       // int idx[128]                                  512
#define SM_RED    102912       // float red[256]                               1024
#define SM_TOTAL  103936

// ---------------- helpers ----------------
__device__ __forceinline__ uint32_t smem_u32(const void* p) {
    uint32_t a;
    asm("{ .reg .u64 t; cvta.to.shared.u64 t, %1; cvt.u32.u64 %0, t; }" : "=r"(a) : "l"(p));
    return a;
}
__device__ __forceinline__ void ldmx4(uint32_t* r, uint32_t addr) {
    asm volatile("ldmatrix.sync.aligned.m8n8.x4.shared.b16 {%0,%1,%2,%3}, [%4];"
        : "=r"(r[0]), "=r"(r[1]), "=r"(r[2]), "=r"(r[3]) : "r"(addr));
}
__device__ __forceinline__ void mma16816(float* c, const uint32_t* a, uint32_t b0, uint32_t b1) {
    asm("mma.sync.aligned.m16n8k16.row.col.f32.f16.f16.f32 "
        "{%0,%1,%2,%3}, {%4,%5,%6,%7}, {%8,%9}, {%0,%1,%2,%3};"
        : "+f"(c[0]), "+f"(c[1]), "+f"(c[2]), "+f"(c[3])
        : "r"(a[0]), "r"(a[1]), "r"(a[2]), "r"(a[3]), "r"(b0), "r"(b1));
}

// exact fp32 rescore of code k — association matches the known-good R1/R7/R13
// exact path VERBATIM (this association produced rel_err 0.0).
__device__ __forceinline__ void rescore(int k, const float* __restrict__ zrow,
                                        const float* __restrict__ emb,
                                        const float* __restrict__ s_e2,
                                        float& best, int& bidx) {
    const float4* e4 = reinterpret_cast<const float4*>(emb + k * CDIM);
    const float4* z4 = reinterpret_cast<const float4*>(zrow);
    float a0 = 0.f, a1 = 0.f, a2 = 0.f, a3 = 0.f;
#pragma unroll
    for (int i = 0; i < 16; i++) {
        float4 e = __ldg(&e4[i]);
        float4 z = z4[i];
        a0 = fmaf(z.x, e.x, a0);
        a1 = fmaf(z.y, e.y, a1);
        a2 = fmaf(z.z, e.z, a2);
        a3 = fmaf(z.w, e.w, a3);
    }
    float dot = (a0 + a1) + (a2 + a3);
    float d = s_e2[k] - 2.0f * dot;
    if (d < best || (d == best && k < bidx)) { best = d; bidx = k; }
}

// cp.async prefetch of one 128-code fp16 chunk into a swizzled smem buffer
__device__ __forceinline__ void prefetch_chunk(uint32_t dstbase, int k0, int tid) {
#pragma unroll
    for (int i = tid; i < 1024; i += THREADS) {   // 1024 x 16B pieces
        int row = i >> 3, sect = i & 7;
        uint32_t dst = dstbase + row * 128 + ((sect ^ (row & 7)) << 4);
        const char* src = (const char*)g_ehf + (size_t)(k0 + row) * 128 + sect * 16;
        asm volatile("cp.async.cg.shared.global [%0], [%1], 16;" :: "r"(dst), "l"(src));
    }
}

// ---------------------------------------------------------------------------
// Pass -1: empty warm kernel (aligns ncu -s 5 capture slot onto vq_kernel)
// ---------------------------------------------------------------------------
__global__ void warm_kernel() {}

// ---------------------------------------------------------------------------
// Pass 0a: ||e||^2 — VERBATIM numerics from the known-passing R1 e2_kernel
// ---------------------------------------------------------------------------
__global__ void e2_kernel(const float* __restrict__ emb) {
    int k = blockIdx.x * blockDim.x + threadIdx.x;
    if (k < KCODES) {
        const float4* row = reinterpret_cast<const float4*>(emb + k * CDIM);
        float s = 0.f;
#pragma unroll
        for (int i = 0; i < 16; i++) {
            float4 v = row[i];
            s += v.x * v.x + v.y * v.y + v.z * v.z + v.w * v.w;
        }
        g_e2[k] = s;
    }
}

// ---------------------------------------------------------------------------
// Pass 0b: fp16 codebook
// ---------------------------------------------------------------------------
__global__ void cvt_kernel(const float* __restrict__ emb) {
    int i = blockIdx.x * blockDim.x + threadIdx.x;
    if (i < KCODES * CDIM / 2) {
        float2 f = reinterpret_cast<const float2*>(emb)[i];
        __half2 h = __floats2half2_rn(f.x, f.y);
        reinterpret_cast<uint32_t*>(g_ehf)[i] = *reinterpret_cast<uint32_t*>(&h);
    }
}

// ---------------------------------------------------------------------------
// Pass 1: mma distance GEMM, candidate collection, deferred exact rescore
// ---------------------------------------------------------------------------
__global__ __launch_bounds__(THREADS, 2)
void vq_kernel(const float* __restrict__ x,
               const float* __restrict__ emb,
               float* __restrict__ out) {
    extern __shared__ char smem[];
    const uint32_t sbase = smem_u32(smem);
    float* s_e2  = reinterpret_cast<float*>(smem + SM_E2);
    float* s_A32 = reinterpret_cast<float*>(smem + SM_A32);
    int*   s_idx = reinterpret_cast<int*>(smem + SM_IDX);
    float* s_red = reinterpret_cast<float*>(smem + SM_RED);

    const int tid  = threadIdx.x;
    const int lane = tid & 31;
    const int wid  = tid >> 5;

    // kick off B chunks 0 and 1 (ring buffers 0,1); overlap with fills below
    prefetch_chunk(sbase + SM_B + 0 * 16384, 0, tid);
    asm volatile("cp.async.commit_group;" ::: "memory");
    prefetch_chunk(sbase + SM_B + 1 * 16384, 128, tid);
    asm volatile("cp.async.commit_group;" ::: "memory");

    // ---- e2 ----
#pragma unroll
    for (int i = tid; i < KCODES; i += THREADS) s_e2[i] = g_e2[i];

    // ---- fill A (fp32 + fp16 swizzled); row r = position, cols = channels ----
    {
        const int r    = tid & 127;
        const int half = tid >> 7;                 // 0: ch 0..31, 1: ch 32..63
        const int p    = blockIdx.x * TILE_M + r;
        const int b    = p >> 12;
        const int hw   = p & (HW - 1);
        const float* xp = x + (size_t)b * CDIM * HW + hw;
#pragma unroll
        for (int s = 0; s < 4; s++) {
            int sect = half * 4 + s;               // 8 channels per sect
            float f[8];
#pragma unroll
            for (int j = 0; j < 8; j++) f[j] = __ldg(xp + (sect * 8 + j) * HW);
            uint4 v;
            uint32_t* vp = &v.x;
#pragma unroll
            for (int j = 0; j < 4; j++) {
                __half2 h = __floats2half2_rn(f[2 * j], f[2 * j + 1]);
                vp[j] = *reinterpret_cast<uint32_t*>(&h);
            }
            *reinterpret_cast<uint4*>(smem + SM_A16 + r * 128 + ((sect ^ (r & 7)) << 4)) = v;
#pragma unroll
            for (int j = 0; j < 8; j++) s_A32[r * CDIM + sect * 8 + j] = f[j];
        }
    }
    __syncthreads();   // A16/A32/e2 visible

    // ---- per-warp GEMM setup: rows m0..m0+15 ----
    const int m0   = wid * 16;
    const int qrow = lane >> 2;
    const int qcol = (lane & 3) * 2;
    const int rA   = m0 + qrow;
    const int rB   = rA + 8;
    const float* zA = s_A32 + rA * CDIM;
    const float* zB = s_A32 + rB * CDIM;

    // A fragments (once)
    uint32_t afr[4][4];
    {
        const uint32_t arow = (uint32_t)(m0 + (lane & 7) + ((lane >> 3) & 1) * 8);
        const uint32_t asb  = (uint32_t)(lane >> 4);
        const uint32_t asx  = (uint32_t)(lane & 7);
#pragma unroll
        for (int ks = 0; ks < 4; ks++)
            ldmx4(afr[ks], sbase + SM_A16 + arow * 128 + ((((ks << 1) | asb) ^ asx) << 4));
    }

    // B lane addressing constants (rows local to chunk buffer)
    const uint32_t brow_off = (uint32_t)(((lane >> 4) * 8 + (lane & 7)) * 128);
    const uint32_t bsb      = (uint32_t)((lane >> 3) & 1);
    const uint32_t bsx      = (uint32_t)(lane & 7);

    // approx running minima + candidate buffers (rescore deferred out of loop)
    float apxA = 3.4e38f, apxB = 3.4e38f;
    uint32_t candA[CAP], candB[CAP];
    int cntA = 0, cntB = 0;
    float ovA = 3.4e38f, ovB = 3.4e38f;      // overflow-fallback exact bests
    int   oviA = 0x7fffffff, oviB = 0x7fffffff;

#pragma unroll 1
    for (int cb = 0; cb < NCHUNKS; cb++) {
        // G_cb must be complete; G_{cb+1} may stay in flight
        if (cb < NCHUNKS - 1) asm volatile("cp.async.wait_group 1;" ::: "memory");
        else                  asm volatile("cp.async.wait_group 0;" ::: "memory");
        __syncthreads();   // (a) all threads' G_cb pieces visible
                           // (b) all warps done reading buf[(cb-1)%3] -> safe to refill

        if (cb + 2 < NCHUNKS) {
            prefetch_chunk(sbase + SM_B + ((cb + 2) % 3) * 16384, (cb + 2) * 128, tid);
            asm volatile("cp.async.commit_group;" ::: "memory");
        }

        const uint32_t bufbase = sbase + SM_B + (cb % 3) * 16384;
        const int n0 = cb * 128;

#pragma unroll 1
        for (int sg = 0; sg < 2; sg++) {          // 64 codes per segment
            float c[8][4];
#pragma unroll
            for (int t = 0; t < 8; t++)
#pragma unroll
                for (int j = 0; j < 4; j++) c[t][j] = 0.f;

#pragma unroll
            for (int tp = 0; tp < 4; tp++) {      // 16 codes per pair
                const uint32_t nbl = (uint32_t)(sg * 64 + tp * 16);
                uint32_t bfr[4][4];
#pragma unroll
                for (int ks = 0; ks < 4; ks++)
                    ldmx4(bfr[ks], bufbase + nbl * 128 + brow_off
                                   + ((((ks << 1) | bsb) ^ bsx) << 4));
#pragma unroll
                for (int ks = 0; ks < 4; ks++) {
                    mma16816(c[tp * 2],     afr[ks], bfr[ks][0], bfr[ks][1]);
                    mma16816(c[tp * 2 + 1], afr[ks], bfr[ks][2], bfr[ks][3]);
                }
            }

            const int kb = n0 + sg * 64;
            // d_apx = e2 - 2*dot
#pragma unroll
            for (int t = 0; t < 8; t++) {
                float2 e2v = *reinterpret_cast<const float2*>(&s_e2[kb + t * 8 + qcol]);
                c[t][0] = fmaf(c[t][0], -2.f, e2v.x);
                c[t][1] = fmaf(c[t][1], -2.f, e2v.y);
                c[t][2] = fmaf(c[t][2], -2.f, e2v.x);
                c[t][3] = fmaf(c[t][3], -2.f, e2v.y);
            }

            // update approx minima, then collect candidates under margin
#pragma unroll
            for (int t = 0; t < 8; t++) {
                apxA = fminf(apxA, fminf(c[t][0], c[t][1]));
                apxB = fminf(apxB, fminf(c[t][2], c[t][3]));
            }
            const float thrA = apxA + MARGIN, thrB = apxB + MARGIN;
            unsigned mA = 0, mB = 0;
#pragma unroll
            for (int t = 0; t < 8; t++) {
                mA |= (c[t][0] < thrA ? 1u : 0u) << (2 * t);
                mA |= (c[t][1] < thrA ? 2u : 0u) << (2 * t);
                mB |= (c[t][2] < thrB ? 1u : 0u) << (2 * t);
                mB |= (c[t][3] < thrB ? 2u : 0u) << (2 * t);
            }
            while (mA) {
                int bpos = __ffs(mA) - 1; mA &= mA - 1;
                int k = kb + (bpos >> 1) * 8 + qcol + (bpos & 1);
                if (cntA < CAP) candA[cntA++] = (uint32_t)k;
                else            rescore(k, zA, emb, s_e2, ovA, oviA);   // ~never
            }
            while (mB) {
                int bpos = __ffs(mB) - 1; mB &= mB - 1;
                int k = kb + (bpos >> 1) * 8 + qcol + (bpos & 1);
                if (cntB < CAP) candB[cntB++] = (uint32_t)k;
                else            rescore(k, zB, emb, s_e2, ovB, oviB);   // ~never
            }
        }
        // NOTE: no end-of-chunk barrier — next iteration's sync protects reuse
    }

    // ---- deferred exact rescoring (no barriers; warps free-run) ----
    float bestA = ovA, bestB = ovB;
    int   idxA  = oviA, idxB = oviB;
    for (int i = 0; i < cntA; i++) rescore((int)candA[i], zA, emb, s_e2, bestA, idxA);
    for (int i = 0; i < cntB; i++) rescore((int)candB[i], zB, emb, s_e2, bestB, idxB);

    // reduce across the 4 lanes of each row quad (exact fp32 values + idx tiebreak)
#pragma unroll
    for (int off = 1; off < 4; off <<= 1) {
        float ob = __shfl_xor_sync(0xffffffffu, bestA, off);
        int   oi = __shfl_xor_sync(0xffffffffu, idxA,  off);
        if (ob < bestA || (ob == bestA && oi < idxA)) { bestA = ob; idxA = oi; }
        ob = __shfl_xor_sync(0xffffffffu, bestB, off);
        oi = __shfl_xor_sync(0xffffffffu, idxB,  off);
        if (ob < bestB || (ob == bestB && oi < idxB)) { bestB = ob; idxB = oi; }
    }
    if ((lane & 3) == 0) { s_idx[rA] = idxA; s_idx[rB] = idxB; }
    __syncthreads();

    // ---- output: o = x + (e - x), indices, loss partial ----
    {
        const int r    = tid & 127;
        const int half = tid >> 7;
        const int p    = blockIdx.x * TILE_M + r;
        const int b    = p >> 12;
        const int hw   = p & (HW - 1);
        const int k    = s_idx[r];
        const float* er = emb + k * CDIM;
        const float* zr = s_A32 + r * CDIM;
        float* op = out + (size_t)b * CDIM * HW + hw;
        float ls = 0.f;
#pragma unroll
        for (int j = 0; j < 32; j++) {
            int ch = half * 32 + j;
            float xv = zr[ch];
            float ev = __ldg(er + ch);
            op[ch * HW] = xv + (ev - xv);           // match reference fp32 ops
            float d = xv - ev;
            ls = fmaf(d, d, ls);
        }
        if (half == 0) out[XSIZE + 1 + p] = (float)k;

        s_red[tid] = ls;
        __syncthreads();
#pragma unroll
        for (int s = THREADS / 2; s > 0; s >>= 1) {
            if (tid < s) s_red[tid] += s_red[tid + s];
            __syncthreads();
        }
        if (tid == 0) g_partials[blockIdx.x] = s_red[0];
    }
}

// ---------------------------------------------------------------------------
// Pass 2: deterministic loss finalize
// ---------------------------------------------------------------------------
__global__ void finalize_kernel(float* __restrict__ out) {
    __shared__ double sd[NBLOCKS];
    int t = threadIdx.x;
    sd[t] = (double)g_partials[t];
    __syncthreads();
#pragma unroll
    for (int s = NBLOCKS / 2; s > 0; s >>= 1) {
        if (t < s) sd[t] += sd[t + s];
        __syncthreads();
    }
    if (t == 0) out[XSIZE] = (float)(1.25 * sd[0] / (double)XSIZE);
}

// ---------------------------------------------------------------------------
extern "C" void kernel_launch(void* const* d_in, const int* in_sizes, int n_in,
                              void* d_out, int out_size) {
    const float* x   = (const float*)d_in[0];
    const float* emb = (const float*)d_in[1];
    if (n_in >= 2 && in_sizes[0] == KCODES * CDIM && in_sizes[1] == XSIZE) {
        const float* t = x; x = emb; emb = t;
    }
    float* out = (float*)d_out;

    cudaFuncSetAttribute(vq_kernel, cudaFuncAttributeMaxDynamicSharedMemorySize, SM_TOTAL);

    warm_kernel<<<1, 32>>>();   // profile-slot alignment (ncu -s 5 -> vq_kernel)
    e2_kernel<<<(KCODES + 255) / 256, 256>>>(emb);
    cvt_kernel<<<(KCODES * CDIM / 2 + 255) / 256, 256>>>(emb);
    vq_kernel<<<NBLOCKS, THREADS, SM_TOTAL>>>(x, emb, out);
    finalize_kernel<<<1, NBLOCKS>>>(out);
}